// round 2
// baseline (speedup 1.0000x reference)
#include <cuda_runtime.h>
#include <math.h>

#define T_  512
#define B_  2048
#define I_  24
#define H_  20
#define NB  4              // batch elements per block
#define TPE 40             // threads per element: 4 gates x 10 row-pairs
#define NTHREADS (NB*TPE)  // 160

typedef unsigned long long u64;

__device__ __forceinline__ u64 pack2(float lo, float hi) {
    u64 r; asm("mov.b64 %0,{%1,%2};" : "=l"(r) : "f"(lo), "f"(hi)); return r;
}
__device__ __forceinline__ void unpack2(u64 v, float& lo, float& hi) {
    asm("mov.b64 {%0,%1},%2;" : "=f"(lo), "=f"(hi) : "l"(v));
}
__device__ __forceinline__ u64 ffma2(u64 a, u64 b, u64 c) {
    u64 d; asm("fma.rn.f32x2 %0,%1,%2,%3;" : "=l"(d) : "l"(a), "l"(b), "l"(c)); return d;
}
__device__ __forceinline__ u64 fadd2(u64 a, u64 b) {
    u64 d; asm("add.rn.f32x2 %0,%1,%2;" : "=l"(d) : "l"(a), "l"(b)); return d;
}
__device__ __forceinline__ float tanhx(float x) {
    float r; asm("tanh.approx.f32 %0,%1;" : "=f"(r) : "f"(x)); return r;
}
__device__ __forceinline__ float sigx(float x) {          // sigmoid via HW tanh
    return fmaf(0.5f, tanhx(0.5f * x), 0.5f);
}

__global__ __launch_bounds__(NTHREADS, 3)
void providence_lstm_kernel(const float* __restrict__ x,
                            const int*   __restrict__ lens,
                            const float* __restrict__ Wih,
                            const float* __restrict__ Whh,
                            const float* __restrict__ bih,
                            const float* __restrict__ bhh,
                            const float* __restrict__ Wa,
                            const float* __restrict__ ba,
                            const float* __restrict__ Wb,
                            const float* __restrict__ bb,
                            float* __restrict__ out)
{
    // All dynamic operands duplicated as (v,v) u64 pairs for packed FFMA2.
    __shared__ __align__(16) u64 xs[2][NB][I_];   // x[t] slice, double-buffered
    __shared__ __align__(16) u64 hs[NB][H_];      // hidden state (h,h)
    __shared__ u64   gs[NB][4][10];               // gates: (row jj, row jj+10)
    __shared__ u64   wab2[H_];                    // (Wa[k], Wb[k])
    __shared__ float2 bab;

    const int tid  = threadIdx.x;
    const int e    = tid / TPE;            // element in block
    const int r    = tid % TPE;            // role 0..39
    const int g    = r / 10;               // gate type i,f,g,o
    const int jj   = r % 10;               // row-pair index
    const int bg   = blockIdx.x * NB + e;  // global batch index
    const unsigned lane = tid & 31u;

    const int row0 = g * H_ + jj;
    const int row1 = row0 + 10;

    // Packed weights in registers: (w_row0, w_row1) pairs. 44 u64 = 88 regs.
    u64 wx[I_], wh[H_];
    #pragma unroll
    for (int i = 0; i < I_; i++) wx[i] = pack2(Wih[row0*I_ + i], Wih[row1*I_ + i]);
    #pragma unroll
    for (int k = 0; k < H_; k++) wh[k] = pack2(Whh[row0*H_ + k], Whh[row1*H_ + k]);
    const u64 biasp = pack2(bih[row0] + bhh[row0], bih[row1] + bhh[row1]);

    if (tid < H_) wab2[tid] = pack2(Wa[tid], Wb[tid]);
    if (tid == 0) bab = make_float2(ba[0], bb[0]);
    if (r < H_)   hs[e][r] = 0ull;
    float c = 0.0f;                        // cell state (threads r < 20)

    const int mylen = lens[bg];

    // preload x[0] duplicated
    if (r < I_) {
        float v = x[(size_t)bg * I_ + r];
        xs[0][e][r] = pack2(v, v);
    }
    const float* xp = x + (size_t)(B_ * I_) + (size_t)bg * I_ + r;  // -> x[1]
    __syncthreads();

    #pragma unroll 2
    for (int t = 0; t < T_; t++) {
        const int cur = t & 1;

        // issue next-x prefetch early (latency hidden behind phase A)
        float xpref = 0.0f;
        const bool doPref = (r < I_) && (t + 1 < T_);
        if (doPref) xpref = *xp;
        xp += B_ * I_;

        // ---- Phase A: 2 gate rows, packed. 22 LDS.128 + 44 FFMA2 ----
        const ulonglong2* xq = (const ulonglong2*)xs[cur][e];  // 12 entries
        const ulonglong2* hq = (const ulonglong2*)hs[e];       // 10 entries
        u64 a0 = biasp, a1 = 0ull;
        #pragma unroll
        for (int j = 0; j < I_/2; j++) {
            ulonglong2 q = xq[j];
            a0 = ffma2(wx[2*j],   q.x, a0);
            a1 = ffma2(wx[2*j+1], q.y, a1);
        }
        #pragma unroll
        for (int j = 0; j < H_/2; j++) {
            ulonglong2 q = hq[j];
            a0 = ffma2(wh[2*j],   q.x, a0);
            a1 = ffma2(wh[2*j+1], q.y, a1);
        }
        gs[e][g][jj] = fadd2(a0, a1);

        if (doPref) xs[cur ^ 1][e][r] = pack2(xpref, xpref);

        __syncthreads();

        // ---- Phase B: state update, unit r per element (r < 20) ----
        if (r < H_) {
            const float* gp = (const float*)gs[e];   // 80 floats
            const int off = (r < 10) ? 2*r : 2*(r-10) + 1;
            float gi = gp[ 0 + off];
            float gf = gp[20 + off];
            float gg = gp[40 + off];
            float go = gp[60 + off];
            c = fmaf(sigx(gf), c, sigx(gi) * tanhx(gg));
            float h = sigx(go) * tanhx(c);
            hs[e][r] = pack2(h, h);
        }
        __syncthreads();

        // ---- Phase C: packed (alpha,beta) head over a 4-lane quad ----
        if (r >= 20 && r < 24) {
            const int q = r - 20;
            u64 z = 0ull;
            #pragma unroll
            for (int j = 0; j < 5; j++) {
                const int k = q * 5 + j;
                z = ffma2(hs[e][k], wab2[k], z);
            }
            const unsigned qmask = 0xFu << (lane & ~3u);
            z = fadd2(z, __shfl_xor_sync(qmask, z, 1));
            z = fadd2(z, __shfl_xor_sync(qmask, z, 2));
            if (q == 0) {
                float za, zb; unpack2(z, za, zb);
                if (t >= mylen) { za = 0.0f; zb = 0.0f; }  // h==0 region
                za += bab.x;  zb += bab.y;
                out[(size_t)t * B_ + bg] = __expf(za);                    // alpha
                float sp = fmaxf(zb, 0.0f) + __logf(1.0f + __expf(-fabsf(zb)));
                out[(size_t)(T_ * B_) + (size_t)t * B_ + bg] = sp;        // beta
            }
        }
    }
}

extern "C" void kernel_launch(void* const* d_in, const int* in_sizes, int n_in,
                              void* d_out, int out_size)
{
    const float *x = 0, *Wih = 0, *Whh = 0, *bih = 0, *bhh = 0;
    const float *Wa = 0, *ba = 0, *Wb = 0, *bb = 0;
    const int *lens = 0;
    int seen80 = 0, seen20 = 0, seen1 = 0;
    for (int i = 0; i < n_in; i++) {
        int s = in_sizes[i];
        if      (s == T_ * B_ * I_) x    = (const float*)d_in[i];
        else if (s == B_)           lens = (const int*)d_in[i];
        else if (s == 4*H_ * I_)    Wih  = (const float*)d_in[i];
        else if (s == 4*H_ * H_)    Whh  = (const float*)d_in[i];
        else if (s == 4*H_) { if (seen80++ == 0) bih = (const float*)d_in[i]; else bhh = (const float*)d_in[i]; }
        else if (s == H_)   { if (seen20++ == 0) Wa  = (const float*)d_in[i]; else Wb  = (const float*)d_in[i]; }
        else if (s == 1)    { if (seen1++  == 0) ba  = (const float*)d_in[i]; else bb  = (const float*)d_in[i]; }
    }

    float* out = (float*)d_out;
    dim3 grid(B_ / NB);      // 512 blocks
    dim3 block(NTHREADS);    // 160 threads
    providence_lstm_kernel<<<grid, block>>>(x, lens, Wih, Whh, bih, bhh,
                                            Wa, ba, Wb, bb, out);
}

// round 3
// speedup vs baseline: 2.3843x; 2.3843x over previous
#include <cuda_runtime.h>
#include <math.h>

#define T_  512
#define B_  2048
#define I_  24
#define H_  20

// Scratch: xg[t][b][u][g] (g = i,f,g,o), float4-aligned per (t,b,u).
__device__ float4 g_xg[(size_t)T_ * B_ * H_];

__device__ __forceinline__ float tanhx(float x) {
    float r; asm("tanh.approx.f32 %0,%1;" : "=f"(r) : "f"(x)); return r;
}
__device__ __forceinline__ float sigx(float x) {   // sigmoid via HW tanh
    return fmaf(0.5f, tanhx(0.5f * x), 0.5f);
}

// ---------------------------------------------------------------------------
// Kernel 1: xg[t,b,u,:] = W_ih[4 rows of unit u] @ x[t,b,:] + (b_ih+b_hh)
// Block: 160 threads = 8 item-lanes x 20 units. Each block does 512 items.
// Weights for this thread's unit live in registers (96 floats).
// ---------------------------------------------------------------------------
__global__ __launch_bounds__(160, 3)
void xg_kernel(const float* __restrict__ x,
               const float* __restrict__ Wih,
               const float* __restrict__ bih,
               const float* __restrict__ bhh)
{
    __shared__ float xs[8 * I_];          // 8 items x 24 inputs

    const int tid = threadIdx.x;
    const int j   = tid / H_;             // item lane 0..7
    const int u   = tid % H_;             // unit 0..19

    // Per-unit weights: rows u (i), 20+u (f), 40+u (g), 60+u (o)
    float w[4][I_];
    #pragma unroll
    for (int g = 0; g < 4; g++)
        #pragma unroll
        for (int k = 0; k < I_; k++)
            w[g][k] = Wih[(g * H_ + u) * I_ + k];
    float4 bias;
    bias.x = bih[0*H_ + u] + bhh[0*H_ + u];
    bias.y = bih[1*H_ + u] + bhh[1*H_ + u];
    bias.z = bih[2*H_ + u] + bhh[2*H_ + u];
    bias.w = bih[3*H_ + u] + bhh[3*H_ + u];

    const size_t item0 = (size_t)blockIdx.x * 512;

    for (int chunk = 0; chunk < 64; chunk++) {
        const size_t base = item0 + (size_t)chunk * 8;
        // stage 8 x-rows (192 floats)
        #pragma unroll
        for (int idx = tid; idx < 8 * I_; idx += 160)
            xs[idx] = x[base * I_ + idx];
        __syncthreads();

        float4 a = bias;
        const float* xr = &xs[j * I_];
        #pragma unroll
        for (int k = 0; k < I_; k++) {
            float xv = xr[k];
            a.x = fmaf(w[0][k], xv, a.x);
            a.y = fmaf(w[1][k], xv, a.y);
            a.z = fmaf(w[2][k], xv, a.z);
            a.w = fmaf(w[3][k], xv, a.w);
        }
        g_xg[(base + j) * H_ + u] = a;
        __syncthreads();
    }
}

// ---------------------------------------------------------------------------
// Kernel 2: recurrence. One warp per batch element. No block barriers,
// no shared memory: h broadcast via SHFL, Whh in registers, xg via
// prefetched LDG.128. Lanes 20..31 mirror lane 0 (zero-weighted in reduce).
// ---------------------------------------------------------------------------
__global__ __launch_bounds__(128, 4)
void recur_kernel(const int*   __restrict__ lens,
                  const float* __restrict__ Whh,
                  const float* __restrict__ Wa,
                  const float* __restrict__ ba,
                  const float* __restrict__ Wb,
                  const float* __restrict__ bb,
                  float* __restrict__ out)
{
    const int lane = threadIdx.x & 31;
    const int wid  = threadIdx.x >> 5;
    const int b    = blockIdx.x * 4 + wid;      // batch element
    const int uu   = (lane < H_) ? lane : 0;    // unit (lanes>=20 mirror u=0)

    // Whh rows for this unit: i, f, g, o  (80 registers)
    float wi[H_], wf[H_], wg[H_], wo[H_];
    #pragma unroll
    for (int k = 0; k < H_; k++) {
        wi[k] = Whh[(0*H_ + uu) * H_ + k];
        wf[k] = Whh[(1*H_ + uu) * H_ + k];
        wg[k] = Whh[(2*H_ + uu) * H_ + k];
        wo[k] = Whh[(3*H_ + uu) * H_ + k];
    }
    const float wa = (lane < H_) ? Wa[lane] : 0.0f;
    const float wb = (lane < H_) ? Wb[lane] : 0.0f;
    const float bav = ba[0], bbv = bb[0];
    // masked-region outputs are constants
    const float alpha_pad = __expf(bav);
    const float beta_pad  = fmaxf(bbv, 0.0f) + __logf(1.0f + __expf(-fabsf(bbv)));
    const int   mylen = lens[b];

    float h = 0.0f, c = 0.0f;

    const float4* xp = &g_xg[(size_t)b * H_ + uu];
    const size_t  xstride = (size_t)B_ * H_;     // per-timestep stride (float4s)

    float4 xg = *xp;                              // prefetch t=0
    xp += xstride;

    float* outA = out + b;
    float* outB = out + (size_t)T_ * B_ + b;

    for (int t = 0; t < T_; t++) {
        float4 nxt;
        if (t + 1 < T_) { nxt = *xp; xp += xstride; }

        float ai = xg.x, af = xg.y, ag = xg.z, ao = xg.w;
        #pragma unroll
        for (int k = 0; k < H_; k++) {
            float hk = __shfl_sync(0xffffffffu, h, k);
            ai = fmaf(wi[k], hk, ai);
            af = fmaf(wf[k], hk, af);
            ag = fmaf(wg[k], hk, ag);
            ao = fmaf(wo[k], hk, ao);
        }

        c = fmaf(sigx(af), c, sigx(ai) * tanhx(ag));
        h = sigx(ao) * tanhx(c);

        // heads: warp butterfly reduce of (h*wa, h*wb)
        float za = h * wa, zb = h * wb;
        #pragma unroll
        for (int off = 16; off >= 1; off >>= 1) {
            za += __shfl_xor_sync(0xffffffffu, za, off);
            zb += __shfl_xor_sync(0xffffffffu, zb, off);
        }
        if (lane == 0) {
            float alpha = (t < mylen) ? __expf(za + bav) : alpha_pad;
            outA[(size_t)t * B_] = alpha;
        } else if (lane == 1) {
            float z = zb + bbv;
            float beta = (t < mylen)
                       ? fmaxf(z, 0.0f) + __logf(1.0f + __expf(-fabsf(z)))
                       : beta_pad;
            outB[(size_t)t * B_] = beta;
        }
        xg = nxt;
    }
}

extern "C" void kernel_launch(void* const* d_in, const int* in_sizes, int n_in,
                              void* d_out, int out_size)
{
    const float *x = 0, *Wih = 0, *Whh = 0, *bih = 0, *bhh = 0;
    const float *Wa = 0, *ba = 0, *Wb = 0, *bb = 0;
    const int *lens = 0;
    int seen80 = 0, seen20 = 0, seen1 = 0;
    for (int i = 0; i < n_in; i++) {
        int s = in_sizes[i];
        if      (s == T_ * B_ * I_) x    = (const float*)d_in[i];
        else if (s == B_)           lens = (const int*)d_in[i];
        else if (s == 4*H_ * I_)    Wih  = (const float*)d_in[i];
        else if (s == 4*H_ * H_)    Whh  = (const float*)d_in[i];
        else if (s == 4*H_) { if (seen80++ == 0) bih = (const float*)d_in[i]; else bhh = (const float*)d_in[i]; }
        else if (s == H_)   { if (seen20++ == 0) Wa  = (const float*)d_in[i]; else Wb  = (const float*)d_in[i]; }
        else if (s == 1)    { if (seen1++  == 0) ba  = (const float*)d_in[i]; else bb  = (const float*)d_in[i]; }
    }

    float* out = (float*)d_out;
    xg_kernel<<<2048, 160>>>(x, Wih, bih, bhh);           // 2048*512 = 1M items
    recur_kernel<<<B_ / 4, 128>>>(lens, Whh, Wa, ba, Wb, bb, out);
}